// round 1
// baseline (speedup 1.0000x reference)
#include <cuda_runtime.h>
#include <math.h>

#define BB   4
#define TT   1024
#define DD   1024
#define DIi  256
#define DCc  1280
#define DFFf 4096
#define HH   16
#define DHh  64
#define SSt  16
#define NNtk 256
#define EEx  1024
#define BT   (BB*TT)            /* 4096  */
#define BSN  (BB*SSt*NNtk)      /* 16384 */
#define NEGV -1e6f

// ---------------- scratch (static device allocations; allowed) ----------------
__device__ float g_q[BT*DD];
__device__ float g_k[BT*DD];
__device__ float g_v[BT*DD];
__device__ float g_scores[(size_t)BB*HH*TT*TT];   // 256 MB, reused by both attns
__device__ float g_merged[BT*DD];
__device__ float g_x2[BT*DD];
__device__ float g_y[BT*DD];
__device__ float g_yi[BT*DCc];
__device__ float g_qs[BT*DD];
__device__ float g_qt[BT*DD];
__device__ float g_ksf[BB*SSt*DD];
__device__ float g_kt[(size_t)BSN*DD];
__device__ float g_vv[(size_t)BSN*DD];
__device__ float g_tsc[(size_t)BT*SSt*NNtk];
__device__ float g_ssc[BT*SSt];
__device__ int   g_selidx[BT*128];
__device__ float g_selw[BT*128];
__device__ int   g_selcnt[BT];
__device__ float g_y2s_raw[BT*DD];
__device__ float g_y2s[BT*DD];
__device__ float g_y2e[BT*DD];
__device__ float g_y2[BT*DD];
__device__ float g_z[BT*DD];
__device__ float g_ffh[(size_t)BT*DFFf];
__device__ float g_ffo[BT*DD];

// ---------------- reductions ----------------
__device__ __forceinline__ float warpRedSum(float v){
#pragma unroll
    for (int o = 16; o > 0; o >>= 1) v += __shfl_xor_sync(0xffffffffu, v, o);
    return v;
}
__device__ __forceinline__ float warpRedMax(float v){
#pragma unroll
    for (int o = 16; o > 0; o >>= 1) v = fmaxf(v, __shfl_xor_sync(0xffffffffu, v, o));
    return v;
}
__device__ __forceinline__ float blockSum(float v, float* sh){
    int lane = threadIdx.x & 31, w = threadIdx.x >> 5;
    v = warpRedSum(v);
    if (lane == 0) sh[w] = v;
    __syncthreads();
    if (w == 0){
        int nw = blockDim.x >> 5;
        float r = (lane < nw) ? sh[lane] : 0.f;
        r = warpRedSum(r);
        if (lane == 0) sh[0] = r;
    }
    __syncthreads();
    float r = sh[0];
    __syncthreads();
    return r;
}
__device__ __forceinline__ float blockMax(float v, float* sh){
    int lane = threadIdx.x & 31, w = threadIdx.x >> 5;
    v = warpRedMax(v);
    if (lane == 0) sh[w] = v;
    __syncthreads();
    if (w == 0){
        int nw = blockDim.x >> 5;
        float r = (lane < nw) ? sh[lane] : -3.4e38f;
        r = warpRedMax(r);
        if (lane == 0) sh[0] = r;
    }
    __syncthreads();
    float r = sh[0];
    __syncthreads();
    return r;
}

// ---------------- SGEMM: C[M,N] = A[M,K] @ B[K,N] (+bias)(+relu) ----------------
__global__ void sgemm_nn(const float* __restrict__ A, const float* __restrict__ Bm,
                         float* __restrict__ C, int M, int Nn, int K,
                         const float* __restrict__ bias, int act)
{
    __shared__ float As[8][128];
    __shared__ float Bs[8][128];
    int tid = threadIdx.x;
    int row0 = blockIdx.y * 128, col0 = blockIdx.x * 128;
    int tx = tid & 15, ty = tid >> 4;
    int ar = tid >> 1, ac = (tid & 1) * 4;
    int br = tid >> 5, bc = (tid & 31) * 4;
    float acc[8][8] = {};
    for (int kk = 0; kk < K; kk += 8){
        float4 av = make_float4(0.f,0.f,0.f,0.f);
        int arow = row0 + ar;
        if (arow < M) av = *reinterpret_cast<const float4*>(A + (size_t)arow*K + kk + ac);
        As[ac+0][ar]=av.x; As[ac+1][ar]=av.y; As[ac+2][ar]=av.z; As[ac+3][ar]=av.w;
        float4 bv = make_float4(0.f,0.f,0.f,0.f);
        int bcol = col0 + bc;
        if (bcol < Nn) bv = *reinterpret_cast<const float4*>(Bm + (size_t)(kk+br)*Nn + bcol);
        *reinterpret_cast<float4*>(&Bs[br][bc]) = bv;
        __syncthreads();
#pragma unroll
        for (int k = 0; k < 8; k++){
            float a[8], b[8];
            *(float4*)&a[0] = *(float4*)&As[k][ty*8];
            *(float4*)&a[4] = *(float4*)&As[k][ty*8+4];
            *(float4*)&b[0] = *(float4*)&Bs[k][tx*8];
            *(float4*)&b[4] = *(float4*)&Bs[k][tx*8+4];
#pragma unroll
            for (int i = 0; i < 8; i++)
#pragma unroll
                for (int j = 0; j < 8; j++) acc[i][j] += a[i]*b[j];
        }
        __syncthreads();
    }
#pragma unroll
    for (int i = 0; i < 8; i++){
        int r = row0 + ty*8 + i;
        if (r >= M) continue;
#pragma unroll
        for (int j = 0; j < 8; j++){
            int c = col0 + tx*8 + j;
            if (c >= Nn) continue;
            float v = acc[i][j];
            if (bias) v += bias[c];
            if (act)  v = fmaxf(v, 0.f);
            C[(size_t)r*Nn + c] = v;
        }
    }
}

// ---------------- batched C[b] = scale * A[b] @ B[b]^T  (A[M,K], B[N,K]) -------
__global__ void sgemm_nt_batched(const float* __restrict__ A, const float* __restrict__ Bmat,
                                 float* __restrict__ C, int M, int Nn, int K,
                                 size_t sA, size_t sB, size_t sC, float scale)
{
    __shared__ float As[8][128];
    __shared__ float Bs[8][128];
    const float* Ab = A + (size_t)blockIdx.z * sA;
    const float* Bb = Bmat + (size_t)blockIdx.z * sB;
    float* Cb = C + (size_t)blockIdx.z * sC;
    int tid = threadIdx.x;
    int row0 = blockIdx.y * 128, col0 = blockIdx.x * 128;
    int tx = tid & 15, ty = tid >> 4;
    int lr = tid >> 1, lc = (tid & 1) * 4;
    float acc[8][8] = {};
    for (int kk = 0; kk < K; kk += 8){
        float4 av = make_float4(0.f,0.f,0.f,0.f);
        int arow = row0 + lr;
        if (arow < M) av = *reinterpret_cast<const float4*>(Ab + (size_t)arow*K + kk + lc);
        As[lc+0][lr]=av.x; As[lc+1][lr]=av.y; As[lc+2][lr]=av.z; As[lc+3][lr]=av.w;
        float4 bv = make_float4(0.f,0.f,0.f,0.f);
        int brow = col0 + lr;
        if (brow < Nn) bv = *reinterpret_cast<const float4*>(Bb + (size_t)brow*K + kk + lc);
        Bs[lc+0][lr]=bv.x; Bs[lc+1][lr]=bv.y; Bs[lc+2][lr]=bv.z; Bs[lc+3][lr]=bv.w;
        __syncthreads();
#pragma unroll
        for (int k = 0; k < 8; k++){
            float a[8], b[8];
            *(float4*)&a[0] = *(float4*)&As[k][ty*8];
            *(float4*)&a[4] = *(float4*)&As[k][ty*8+4];
            *(float4*)&b[0] = *(float4*)&Bs[k][tx*8];
            *(float4*)&b[4] = *(float4*)&Bs[k][tx*8+4];
#pragma unroll
            for (int i = 0; i < 8; i++)
#pragma unroll
                for (int j = 0; j < 8; j++) acc[i][j] += a[i]*b[j];
        }
        __syncthreads();
    }
#pragma unroll
    for (int i = 0; i < 8; i++){
        int r = row0 + ty*8 + i;
        if (r >= M) continue;
#pragma unroll
        for (int j = 0; j < 8; j++){
            int c = col0 + tx*8 + j;
            if (c >= Nn) continue;
            Cb[(size_t)r*Nn + c] = acc[i][j] * scale;
        }
    }
}

// ---------------- attention scores: S[bh,t,tk] = scale * q_h(t)·k_h(tk) -------
__global__ void attn_scores_kernel(const float* __restrict__ Q, const float* __restrict__ Km,
                                   float* __restrict__ Sc, int Tq, int Tk, float scale)
{
    __shared__ float Qs[64][64];
    __shared__ float Kst[64][72];
    int bh = blockIdx.z;
    int b = bh / HH, h = bh % HH;
    const float* qb = Q + (size_t)b*Tq*DD + h*DHh;
    const float* kb = Km + (size_t)b*Tk*DD + h*DHh;
    float* sb = Sc + (size_t)bh*Tq*Tk;
    int t0 = blockIdx.y * 64, k0 = blockIdx.x * 64;
    int tid = threadIdx.x;
    int lr = tid >> 4, lc4 = (tid & 15) * 4;
#pragma unroll
    for (int p = 0; p < 4; p++){
        int r = p*16 + lr;
        float4 qv = *(const float4*)(qb + (size_t)(t0+r)*DD + lc4);
        *(float4*)&Qs[r][lc4] = qv;
        float4 kv = *(const float4*)(kb + (size_t)(k0+r)*DD + lc4);
        Kst[lc4+0][r]=kv.x; Kst[lc4+1][r]=kv.y; Kst[lc4+2][r]=kv.z; Kst[lc4+3][r]=kv.w;
    }
    __syncthreads();
    int ty = tid >> 4, tx = tid & 15;
    float acc[4][4] = {};
#pragma unroll
    for (int d = 0; d < 64; d++){
        float a[4];
#pragma unroll
        for (int i = 0; i < 4; i++) a[i] = Qs[ty*4+i][d];
        float4 bv = *(float4*)&Kst[d][tx*4];
        float b4[4] = {bv.x, bv.y, bv.z, bv.w};
#pragma unroll
        for (int i = 0; i < 4; i++)
#pragma unroll
            for (int j = 0; j < 4; j++) acc[i][j] += a[i]*b4[j];
    }
#pragma unroll
    for (int i = 0; i < 4; i++)
#pragma unroll
        for (int j = 0; j < 4; j++)
            sb[(size_t)(t0+ty*4+i)*Tk + k0 + tx*4 + j] = acc[i][j] * scale;
}

// ---------------- masked softmax over rows of length Tk ----------------
__global__ void softmax_kernel(float* __restrict__ Sc, int Tq, int Tk,
                               int causal, const int* __restrict__ evl)
{
    __shared__ float sh[32];
    int row = blockIdx.x;
    int t = row % Tq;
    int bh = row / Tq;
    int b = bh / HH;
    int vl = causal ? (t + 1) : evl[b];
    float* p = Sc + (size_t)row*Tk;
    int tid = threadIdx.x; // 128, 8 elems each
    float v[8];
    float m = -3.4e38f;
#pragma unroll
    for (int i = 0; i < 8; i++){
        int c = tid + i*128;
        v[i] = p[c];
        if (c < vl) m = fmaxf(m, v[i]);
    }
    m = blockMax(m, sh);
    float s = 0.f;
#pragma unroll
    for (int i = 0; i < 8; i++){
        int c = tid + i*128;
        float e = (c < vl) ? expf(v[i] - m) : 0.f;
        v[i] = e; s += e;
    }
    s = blockSum(s, sh);
    float inv = 1.f / s;
#pragma unroll
    for (int i = 0; i < 8; i++) p[tid + i*128] = v[i] * inv;
}

// ---------------- P@V, writes merged-head layout ----------------
__global__ void attn_pv_kernel(const float* __restrict__ P, const float* __restrict__ V,
                               float* __restrict__ Out, int Tq, int Tk)
{
    __shared__ float Ps[64][64];
    __shared__ float Vs[64][68];
    int bh = blockIdx.y;
    int b = bh / HH, h = bh % HH;
    const float* pb = P + (size_t)bh*Tq*Tk;
    const float* vb = V + (size_t)b*Tk*DD + h*DHh;
    float* ob = Out + (size_t)b*Tq*DD + h*DHh;
    int t0 = blockIdx.x * 64;
    int tid = threadIdx.x;
    int lr = tid >> 4, lc4 = (tid & 15) * 4;
    int ty = tid >> 4, tx = tid & 15;
    float acc[4][4] = {};
    for (int kk = 0; kk < Tk; kk += 64){
#pragma unroll
        for (int p = 0; p < 4; p++){
            int r = p*16 + lr;
            *(float4*)&Ps[r][lc4] = *(const float4*)(pb + (size_t)(t0+r)*Tk + kk + lc4);
            float4 vv4 = *(const float4*)(vb + (size_t)(kk+r)*DD + lc4);
            *(float4*)&Vs[r][lc4] = vv4;
        }
        __syncthreads();
#pragma unroll
        for (int k = 0; k < 64; k++){
            float4 bv = *(float4*)&Vs[k][tx*4];
            float b4[4] = {bv.x, bv.y, bv.z, bv.w};
            float a[4];
#pragma unroll
            for (int i = 0; i < 4; i++) a[i] = Ps[ty*4+i][k];
#pragma unroll
            for (int i = 0; i < 4; i++)
#pragma unroll
                for (int j = 0; j < 4; j++) acc[i][j] += a[i]*b4[j];
        }
        __syncthreads();
    }
#pragma unroll
    for (int i = 0; i < 4; i++)
#pragma unroll
        for (int j = 0; j < 4; j++)
            ob[(size_t)(t0+ty*4+i)*DD + tx*4 + j] = acc[i][j];
}

// ---------------- LN(out) = layernorm(A + sB*B) * g + b ----------------
__global__ void ln_kernel(const float* __restrict__ A, const float* __restrict__ Bm, float sB,
                          const float* __restrict__ gw, const float* __restrict__ bw,
                          float* __restrict__ Out)
{
    __shared__ float sh[32];
    int row = blockIdx.x;
    int tid = threadIdx.x;   // 256, 4 elems each
    float4 a4 = *(const float4*)(A + (size_t)row*DD + tid*4);
    float x[4] = {a4.x, a4.y, a4.z, a4.w};
    if (Bm){
        float4 b4 = *(const float4*)(Bm + (size_t)row*DD + tid*4);
        x[0] += sB*b4.x; x[1] += sB*b4.y; x[2] += sB*b4.z; x[3] += sB*b4.w;
    }
    float s = x[0]+x[1]+x[2]+x[3];
    s = blockSum(s, sh);
    float mean = s * (1.f/DD);
    float q = 0.f;
#pragma unroll
    for (int i = 0; i < 4; i++){ float d = x[i]-mean; q += d*d; }
    q = blockSum(q, sh);
    float rstd = rsqrtf(q * (1.f/DD) + 1e-5f);
#pragma unroll
    for (int i = 0; i < 4; i++){
        int c = tid*4 + i;
        Out[(size_t)row*DD + c] = (x[i]-mean)*rstd*gw[c] + bw[c];
    }
}

// ---------------- yi = [y | intent] ----------------
__global__ void concat_kernel(const float* __restrict__ Y, const float* __restrict__ intent,
                              float* __restrict__ Yi)
{
    int i = blockIdx.x*blockDim.x + threadIdx.x;
    if (i >= BT*DCc) return;
    int row = i / DCc, c = i % DCc;
    float val;
    if (c < DD) val = Y[(size_t)row*DD + c];
    else { int b = row / TT; val = intent[b*DIi + (c - DD)]; }
    Yi[i] = val;
}

// ---------------- ssc[b,t,s] = qs·ks / 32 ----------------
__global__ void ssc_kernel(const float* __restrict__ QS, const float* __restrict__ KS,
                           float* __restrict__ SSC)
{
    __shared__ float qsh[DD];
    int row = blockIdx.x;
    int b = row / TT;
    int tid = threadIdx.x;  // 256
    *(float4*)&qsh[tid*4] = *(const float4*)(QS + (size_t)row*DD + tid*4);
    __syncthreads();
    int w = tid >> 5, lane = tid & 31;
    for (int ss = w; ss < SSt; ss += 8){
        const float* kr = KS + ((size_t)b*SSt + ss)*DD;
        float sum = 0.f;
        for (int j = lane*4; j < DD; j += 128){
            float4 kv = *(const float4*)(kr + j);
            float4 qv = *(const float4*)&qsh[j];
            sum += qv.x*kv.x + qv.y*kv.y + qv.z*kv.z + qv.w*kv.w;
        }
        sum = warpRedSum(sum);
        if (lane == 0) SSC[row*SSt + ss] = sum * (1.f/32.f);
    }
}

// ---------------- per-token stat-softmax (top-8) + token top-16 → sparse comb --
__global__ void sel_topk_kernel(const float* __restrict__ SSC, const float* __restrict__ TSC,
                                const int* __restrict__ svl,
                                int* __restrict__ OutIdx, float* __restrict__ OutW,
                                int* __restrict__ OutCnt)
{
    __shared__ float s_v[SSt];
    __shared__ float s_sw[SSt];
    __shared__ int   s_rank[SSt];
    __shared__ float s_tv[SSt][16];
    __shared__ int   s_ti[SSt][16];
    int row = blockIdx.x;
    int b = row / TT;
    int tid = threadIdx.x;   // 512 = 16 warps
    int w = tid >> 5, lane = tid & 31;
    if (tid < SSt){
        float val = SSC[row*SSt + tid];
        if (tid >= svl[b]) val = NEGV;
        s_v[tid] = val;
    }
    __syncthreads();
    if (tid < SSt){
        float myv = s_v[tid];
        int cnt = 0;
        float m = -3.4e38f;
#pragma unroll
        for (int j = 0; j < SSt; j++){
            float o = s_v[j];
            if (o > myv || (o == myv && j < tid)) cnt++;
            m = fmaxf(m, o);
        }
        s_sw[tid] = (cnt < 8) ? expf(myv - m) : 0.f;   // top-8 kept (ties: lower index)
    }
    __syncthreads();
    if (tid == 0){
        float den = 0.f;
        for (int j = 0; j < SSt; j++) den += s_sw[j];
        float inv = 1.f/den;
        int r = 0;
        for (int j = 0; j < SSt; j++){
            float swv = s_sw[j]*inv;
            s_sw[j] = swv;
            s_rank[j] = r;
            if (swv > 0.f) r++;
        }
        OutCnt[row] = r*16;
    }
    __syncthreads();
    // each warp handles one stat's token top-16
    float swv = s_sw[w];
    if (swv > 0.f){
        const float* tr = TSC + ((size_t)row*SSt + w)*NNtk;
        float vloc[8];
#pragma unroll
        for (int r2 = 0; r2 < 8; r2++) vloc[r2] = tr[r2*32 + lane];
        for (int it = 0; it < 16; it++){
            float bv = -3.4e38f; int bi = 1 << 30;
#pragma unroll
            for (int r2 = 0; r2 < 8; r2++){
                if (vloc[r2] > bv){ bv = vloc[r2]; bi = r2*32 + lane; }
            }
#pragma unroll
            for (int off = 16; off > 0; off >>= 1){
                float ov = __shfl_xor_sync(0xffffffffu, bv, off);
                int   oi = __shfl_xor_sync(0xffffffffu, bi, off);
                if (ov > bv || (ov == bv && oi < bi)){ bv = ov; bi = oi; }
            }
            if (lane == 0){ s_tv[w][it] = bv; s_ti[w][it] = bi; }
            if ((bi & 31) == lane) vloc[bi >> 5] = -3.4e38f;
        }
        __syncwarp();
        float m2 = s_tv[w][0];
        float e2 = (lane < 16) ? expf(s_tv[w][lane] - m2) : 0.f;
        float den2 = warpRedSum(e2);
        if (lane < 16){
            int base = s_rank[w]*16;
            OutW[row*128 + base + lane]   = swv * e2 / den2;
            OutIdx[row*128 + base + lane] = w*NNtk + s_ti[w][lane];
        }
    }
}

// ---------------- y2s_raw[row] = sum_e w_e * vv[b, idx_e, :] ----------------
__global__ void gather_y2s_kernel(const int* __restrict__ Idx, const float* __restrict__ Wt,
                                  const int* __restrict__ Cnt, const float* __restrict__ VV,
                                  float* __restrict__ Out)
{
    __shared__ int   sh_i[128];
    __shared__ float sh_w[128];
    int row = blockIdx.x;
    int b = row / TT;
    int tid = threadIdx.x; // 256
    int cnt = Cnt[row];
    if (tid < 128){ sh_i[tid] = Idx[row*128 + tid]; sh_w[tid] = Wt[row*128 + tid]; }
    __syncthreads();
    const float* vb = VV + (size_t)b*SSt*NNtk*DD;
    float4 acc = make_float4(0.f,0.f,0.f,0.f);
    int c4 = tid*4;
    for (int e = 0; e < cnt; e++){
        float wv = sh_w[e];
        float4 x4 = *(const float4*)(vb + (size_t)sh_i[e]*DD + c4);
        acc.x += wv*x4.x; acc.y += wv*x4.y; acc.z += wv*x4.z; acc.w += wv*x4.w;
    }
    *(float4*)(Out + (size_t)row*DD + c4) = acc;
}

// ---------------- gate + blend ----------------
__global__ void gate_kernel(const float* __restrict__ Y2S, const float* __restrict__ Y2E,
                            const float* __restrict__ Wg, float* __restrict__ Y2)
{
    __shared__ float sh[32];
    int row = blockIdx.x;
    int tid = threadIdx.x; // 256
    int c4 = tid*4;
    float4 a  = *(const float4*)(Y2S + (size_t)row*DD + c4);
    float4 b4 = *(const float4*)(Y2E + (size_t)row*DD + c4);
    float4 w1 = *(const float4*)(Wg + c4);
    float4 w2 = *(const float4*)(Wg + DD + c4);
    float part = a.x*w1.x + a.y*w1.y + a.z*w1.z + a.w*w1.w
               + b4.x*w2.x + b4.y*w2.y + b4.z*w2.z + b4.w*w2.w;
    float dot = blockSum(part, sh);
    float gv = 1.f/(1.f + expf(-dot));
    float4 o;
    o.x = gv*a.x + (1.f-gv)*b4.x;
    o.y = gv*a.y + (1.f-gv)*b4.y;
    o.z = gv*a.z + (1.f-gv)*b4.z;
    o.w = gv*a.w + (1.f-gv)*b4.w;
    *(float4*)(Y2 + (size_t)row*DD + c4) = o;
}

// ---------------- launch ----------------
extern "C" void kernel_launch(void* const* d_in, const int* in_sizes, int n_in,
                              void* d_out, int out_size)
{
    const float* x        = (const float*)d_in[0];
    const float* stat_enc = (const float*)d_in[1];
    const float* ex       = (const float*)d_in[2];
    const float* stat_ft  = (const float*)d_in[3];
    const float* intent   = (const float*)d_in[4];
    const float* Wq1=(const float*)d_in[5],  *Wk1=(const float*)d_in[6];
    const float* Wv1=(const float*)d_in[7],  *Wo1=(const float*)d_in[8];
    const float* Wq_stat=(const float*)d_in[9],  *Wq_token=(const float*)d_in[10];
    const float* Wk_stat=(const float*)d_in[11], *Wk_token=(const float*)d_in[12];
    const float* Wv_sel=(const float*)d_in[13],  *Wo_sel=(const float*)d_in[14];
    const float* Wq2=(const float*)d_in[15], *Wk2=(const float*)d_in[16];
    const float* Wv2=(const float*)d_in[17], *Wo2=(const float*)d_in[18];
    const float* Wg=(const float*)d_in[19];
    const float* W1=(const float*)d_in[20], *b1=(const float*)d_in[21];
    const float* W2=(const float*)d_in[22], *b2=(const float*)d_in[23];
    const float* w_g1=(const float*)d_in[24], *w_be1=(const float*)d_in[25];
    const float* w_g2=(const float*)d_in[26], *w_be2=(const float*)d_in[27];
    const float* w_g3=(const float*)d_in[28], *w_be3=(const float*)d_in[29];
    const int* svl = (const int*)d_in[30];
    const int* evl = (const int*)d_in[31];
    float* out = (float*)d_out;

    float *pq,*pk,*pv,*psc,*pm,*px2,*py,*pyi,*pqs,*pqt,*pks,*pkt,*pvv,*ptsc,*pssc;
    float *py2sr,*py2s,*py2e,*py2,*pz,*pffh,*pffo,*pselw;
    int *pselidx,*pselcnt;
    cudaGetSymbolAddress((void**)&pq, g_q);
    cudaGetSymbolAddress((void**)&pk, g_k);
    cudaGetSymbolAddress((void**)&pv, g_v);
    cudaGetSymbolAddress((void**)&psc, g_scores);
    cudaGetSymbolAddress((void**)&pm, g_merged);
    cudaGetSymbolAddress((void**)&px2, g_x2);
    cudaGetSymbolAddress((void**)&py, g_y);
    cudaGetSymbolAddress((void**)&pyi, g_yi);
    cudaGetSymbolAddress((void**)&pqs, g_qs);
    cudaGetSymbolAddress((void**)&pqt, g_qt);
    cudaGetSymbolAddress((void**)&pks, g_ksf);
    cudaGetSymbolAddress((void**)&pkt, g_kt);
    cudaGetSymbolAddress((void**)&pvv, g_vv);
    cudaGetSymbolAddress((void**)&ptsc, g_tsc);
    cudaGetSymbolAddress((void**)&pssc, g_ssc);
    cudaGetSymbolAddress((void**)&pselw, g_selw);
    cudaGetSymbolAddress((void**)&pselidx, g_selidx);
    cudaGetSymbolAddress((void**)&pselcnt, g_selcnt);
    cudaGetSymbolAddress((void**)&py2sr, g_y2s_raw);
    cudaGetSymbolAddress((void**)&py2s, g_y2s);
    cudaGetSymbolAddress((void**)&py2e, g_y2e);
    cudaGetSymbolAddress((void**)&py2, g_y2);
    cudaGetSymbolAddress((void**)&pz, g_z);
    cudaGetSymbolAddress((void**)&pffh, g_ffh);
    cudaGetSymbolAddress((void**)&pffo, g_ffo);

    auto gemm = [&](const float* A, const float* Bm, float* C, int M, int Nn, int K,
                    const float* bias, int act){
        dim3 grid((Nn + 127)/128, (M + 127)/128);
        sgemm_nn<<<grid, 256>>>(A, Bm, C, M, Nn, K, bias, act);
    };

    // ---- self attention ----
    gemm(x, Wq1, pq, BT, DD, DD, nullptr, 0);
    gemm(x, Wk1, pk, BT, DD, DD, nullptr, 0);
    gemm(x, Wv1, pv, BT, DD, DD, nullptr, 0);
    attn_scores_kernel<<<dim3(TT/64, TT/64, BB*HH), 256>>>(pq, pk, psc, TT, TT, 0.125f);
    softmax_kernel<<<BB*HH*TT, 128>>>(psc, TT, TT, 1, nullptr);
    attn_pv_kernel<<<dim3(TT/64, BB*HH), 256>>>(psc, pv, pm, TT, TT);
    gemm(pm, Wo1, px2, BT, DD, DD, nullptr, 0);
    ln_kernel<<<BT, 256>>>(x, px2, 1.f, w_g1, w_be1, py);

    // ---- selective hierarchical top-k ----
    concat_kernel<<<(BT*DCc + 255)/256, 256>>>(py, intent, pyi);
    gemm(pyi, Wq_stat, pqs, BT, DD, DCc, nullptr, 0);
    gemm(pyi, Wq_token, pqt, BT, DD, DCc, nullptr, 0);
    gemm(stat_ft, Wk_stat, pks, BB*SSt, DD, DD, nullptr, 0);
    gemm(stat_enc, Wk_token, pkt, BSN, DD, DD, nullptr, 0);
    gemm(stat_enc, Wv_sel, pvv, BSN, DD, DD, nullptr, 0);
    ssc_kernel<<<BT, 256>>>(pqs, pks, pssc);
    sgemm_nt_batched<<<dim3((SSt*NNtk)/128, TT/128, BB), 256>>>(
        pqt, pkt, ptsc, TT, SSt*NNtk, DD,
        (size_t)TT*DD, (size_t)SSt*NNtk*DD, (size_t)TT*SSt*NNtk, 1.f/32.f);
    sel_topk_kernel<<<BT, 512>>>(pssc, ptsc, svl, pselidx, pselw, pselcnt);
    gather_y2s_kernel<<<BT, 256>>>(pselidx, pselw, pselcnt, pvv, py2sr);
    gemm(py2sr, Wo_sel, py2s, BT, DD, DD, nullptr, 0);

    // ---- exemplar cross attention ----
    gemm(pyi, Wq2, pq, BT, DD, DCc, nullptr, 0);
    gemm(ex, Wk2, pk, BB*EEx, DD, DD, nullptr, 0);
    gemm(ex, Wv2, pv, BB*EEx, DD, DD, nullptr, 0);
    attn_scores_kernel<<<dim3(EEx/64, TT/64, BB*HH), 256>>>(pq, pk, psc, TT, EEx, 0.125f);
    softmax_kernel<<<BB*HH*TT, 128>>>(psc, TT, EEx, 0, evl);
    attn_pv_kernel<<<dim3(TT/64, BB*HH), 256>>>(psc, pv, pm, TT, EEx);
    gemm(pm, Wo2, py2e, BT, DD, DD, nullptr, 0);

    // ---- gate, LN, FFN, LN ----
    gate_kernel<<<BT, 256>>>(py2s, py2e, Wg, py2);
    ln_kernel<<<BT, 256>>>(py, py2, 2.f, w_g2, w_be2, pz);
    gemm(pz, W1, pffh, BT, DFFf, DD, b1, 1);
    gemm(pffh, W2, pffo, BT, DD, DFFf, b2, 0);
    ln_kernel<<<BT, 256>>>(pz, pffo, 1.f, w_g3, w_be3, out);
}

// round 3
// speedup vs baseline: 1.0783x; 1.0783x over previous
#include <cuda_runtime.h>
#include <math.h>

#define BB   4
#define TT   1024
#define DD   1024
#define DIi  256
#define DCc  1280
#define DFFf 4096
#define HH   16
#define DHh  64
#define SSt  16
#define NNtk 256
#define EEx  1024
#define BT   (BB*TT)            /* 4096  */
#define BSN  (BB*SSt*NNtk)      /* 16384 */
#define NEGV -1e6f
#define BKk  16

// ---------------- scratch ----------------
__device__ float g_q[BT*DD];
__device__ float g_k[BT*DD];
__device__ float g_v[BT*DD];
__device__ float g_scores[(size_t)BB*HH*TT*TT];
__device__ float g_merged[BT*DD];
__device__ float g_x2[BT*DD];
__device__ float g_y[BT*DD];
__device__ float g_yi[BT*DCc];
__device__ float g_qs[BT*DD];
__device__ float g_qt[BT*DD];
__device__ float g_ksf[BB*SSt*DD];
__device__ float g_kt[(size_t)BSN*DD];
__device__ float g_vv[(size_t)BSN*DD];
__device__ float g_tsc[(size_t)BT*SSt*NNtk];
__device__ float g_ssc[BT*SSt];
__device__ int   g_selidx[BT*128];
__device__ float g_selw[BT*128];
__device__ int   g_selcnt[BT];
__device__ float g_y2s_raw[BT*DD];
__device__ float g_y2s[BT*DD];
__device__ float g_y2e[BT*DD];
__device__ float g_y2[BT*DD];
__device__ float g_z[BT*DD];
__device__ float g_ffh[(size_t)BT*DFFf];
__device__ float g_ffo[BT*DD];

// ---------------- helpers ----------------
__device__ __forceinline__ unsigned f2tf(float f){
    unsigned r; asm("cvt.rna.tf32.f32 %0, %1;" : "=r"(r) : "f"(f)); return r;
}
__device__ __forceinline__ void split_tf(float f, unsigned& hi, unsigned& lo){
    unsigned h; asm("cvt.rna.tf32.f32 %0, %1;" : "=r"(h) : "f"(f));
    float hf = __uint_as_float(h);
    float lf = f - hf;
    unsigned l; asm("cvt.rna.tf32.f32 %0, %1;" : "=r"(l) : "f"(lf));
    hi = h; lo = l;
}
__device__ __forceinline__ void mma_tf32(float c[4], const unsigned a[4], unsigned b0, unsigned b1){
    asm volatile("mma.sync.aligned.m16n8k8.row.col.f32.tf32.tf32.f32 "
        "{%0,%1,%2,%3},{%4,%5,%6,%7},{%8,%9},{%0,%1,%2,%3};\n"
        : "+f"(c[0]), "+f"(c[1]), "+f"(c[2]), "+f"(c[3])
        : "r"(a[0]), "r"(a[1]), "r"(a[2]), "r"(a[3]), "r"(b0), "r"(b1));
}
__device__ __forceinline__ float warpRedSum(float v){
#pragma unroll
    for (int o = 16; o > 0; o >>= 1) v += __shfl_xor_sync(0xffffffffu, v, o);
    return v;
}
__device__ __forceinline__ float warpRedMax(float v){
#pragma unroll
    for (int o = 16; o > 0; o >>= 1) v = fmaxf(v, __shfl_xor_sync(0xffffffffu, v, o));
    return v;
}
__device__ __forceinline__ float blockSum(float v, float* sh){
    int lane = threadIdx.x & 31, w = threadIdx.x >> 5;
    v = warpRedSum(v);
    if (lane == 0) sh[w] = v;
    __syncthreads();
    if (w == 0){
        int nw = blockDim.x >> 5;
        float r = (lane < nw) ? sh[lane] : 0.f;
        r = warpRedSum(r);
        if (lane == 0) sh[0] = r;
    }
    __syncthreads();
    float r = sh[0];
    __syncthreads();
    return r;
}
__device__ __forceinline__ float blockMax(float v, float* sh){
    int lane = threadIdx.x & 31, w = threadIdx.x >> 5;
    v = warpRedMax(v);
    if (lane == 0) sh[w] = v;
    __syncthreads();
    if (w == 0){
        int nw = blockDim.x >> 5;
        float r = (lane < nw) ? sh[lane] : -3.4e38f;
        r = warpRedMax(r);
        if (lane == 0) sh[0] = r;
    }
    __syncthreads();
    float r = sh[0];
    __syncthreads();
    return r;
}

// ================= 3xTF32 tensor-core GEMM (fp32-accurate) =================
// C = scale * A @ op(B) (+bias)(+relu). A row-major [M,K] lda.
// TRANSB=false: B row-major [K,N] ldb.  TRANSB=true: B row-major [N,K] ldb (C=A@B^T).
// Batched over blockIdx.z with split (batch = z/NH, head = z%NH) offsets.
template<int BM, int BN, bool TRANSB>
__global__ void __launch_bounds__((BM/64)*(BN/32)*32)
gemm_tf32(const float* __restrict__ A, const float* __restrict__ B, float* __restrict__ C,
          int M, int N, int K, int lda, int ldb, int ldc, int NH,
          size_t sAb, size_t sAh, size_t sBb, size_t sBh, size_t sCb, size_t sCh,
          const float* __restrict__ bias, float scale, int act)
{
    constexpr int NWN = BN/32, NWM = BM/64, NW = NWN*NWM, NTH = NW*32;
    constexpr int AV  = (BM*BKk/4)/NTH;
    constexpr int BV  = (TRANSB ? BN*BKk/4 : (BKk*BN/4))/NTH;
    constexpr int BROWS = TRANSB ? BN : BKk;
    constexpr int BCOLS = TRANSB ? (BKk+4) : (BN+8);

    __shared__ unsigned AsH[BM][BKk+4];
    __shared__ unsigned AsL[BM][BKk+4];
    __shared__ unsigned BsH[BROWS][BCOLS];
    __shared__ unsigned BsL[BROWS][BCOLS];

    int z = blockIdx.z;
    const float* Ab = A + (size_t)(z/NH)*sAb + (size_t)(z%NH)*sAh;
    const float* Bb = B + (size_t)(z/NH)*sBb + (size_t)(z%NH)*sBh;
    float*       Cb = C + (size_t)(z/NH)*sCb + (size_t)(z%NH)*sCh;

    int tid = threadIdx.x, lane = tid & 31, wid = tid >> 5;
    int wn = wid % NWN, wm = wid / NWN;
    int row0 = blockIdx.y * BM, col0 = blockIdx.x * BN;
    int g = lane >> 2, tg = lane & 3;

    float acc[4][4][4] = {};
    float4 ra[AV], rb[BV];

    auto fetchA = [&](int kk){
#pragma unroll
        for (int v = 0; v < AV; v++){
            int i = tid + v*NTH;
            int r = i >> 2, c = (i & 3) * 4;
            int gr = row0 + r;
            ra[v] = (gr < M) ? *(const float4*)(Ab + (size_t)gr*lda + kk + c)
                             : make_float4(0.f,0.f,0.f,0.f);
        }
    };
    auto storeA = [&](){
#pragma unroll
        for (int v = 0; v < AV; v++){
            int i = tid + v*NTH;
            int r = i >> 2, c = (i & 3) * 4;
            split_tf(ra[v].x, AsH[r][c+0], AsL[r][c+0]);
            split_tf(ra[v].y, AsH[r][c+1], AsL[r][c+1]);
            split_tf(ra[v].z, AsH[r][c+2], AsL[r][c+2]);
            split_tf(ra[v].w, AsH[r][c+3], AsL[r][c+3]);
        }
    };
    auto fetchB = [&](int kk){
        if (TRANSB){
#pragma unroll
            for (int v = 0; v < BV; v++){
                int i = tid + v*NTH;
                int r = i >> 2, c = (i & 3) * 4;
                int gr = col0 + r;
                rb[v] = (gr < N) ? *(const float4*)(Bb + (size_t)gr*ldb + kk + c)
                                 : make_float4(0.f,0.f,0.f,0.f);
            }
        } else {
            constexpr int VPR = BN/4;
#pragma unroll
            for (int v = 0; v < BV; v++){
                int i = tid + v*NTH;
                int r = i / VPR, c = (i % VPR) * 4;
                int gc = col0 + c;
                rb[v] = (gc < N) ? *(const float4*)(Bb + (size_t)(kk+r)*ldb + gc)
                                 : make_float4(0.f,0.f,0.f,0.f);
            }
        }
    };
    auto storeB = [&](){
        if (TRANSB){
#pragma unroll
            for (int v = 0; v < BV; v++){
                int i = tid + v*NTH;
                int r = i >> 2, c = (i & 3) * 4;
                split_tf(rb[v].x, BsH[r][c+0], BsL[r][c+0]);
                split_tf(rb[v].y, BsH[r][c+1], BsL[r][c+1]);
                split_tf(rb[v].z, BsH[r][c+2], BsL[r][c+2]);
                split_tf(rb[v].w, BsH[r][c+3], BsL[r][c+3]);
            }
        } else {
            constexpr int VPR = BN/4;
#pragma unroll
            for (int v = 0; v < BV; v++){
                int i = tid + v*NTH;
                int r = i / VPR, c = (i % VPR) * 4;
                split_tf(rb[v].x, BsH[r][c+0], BsL[r][c+0]);
                split_tf(rb[v].y, BsH[r][c+1], BsL[r][c+1]);
                split_tf(rb[v].z, BsH[r][c+2], BsL[r][c+2]);
                split_tf(rb[v].w, BsH[r][c+3], BsL[r][c+3]);
            }
        }
    };

    fetchA(0); fetchB(0);
    storeA(); storeB();
    __syncthreads();

    int kiters = K / BKk;
    for (int kt = 0; kt < kiters; kt++){
        if (kt + 1 < kiters){ fetchA((kt+1)*BKk); fetchB((kt+1)*BKk); }
#pragma unroll
        for (int ks = 0; ks < BKk/8; ks++){
            int kk = ks * 8;
            unsigned afH[4][4], afL[4][4];
#pragma unroll
            for (int mt = 0; mt < 4; mt++){
                int mr = wm*64 + mt*16;
                afH[mt][0] = AsH[mr+g  ][kk+tg  ];
                afH[mt][1] = AsH[mr+g+8][kk+tg  ];
                afH[mt][2] = AsH[mr+g  ][kk+tg+4];
                afH[mt][3] = AsH[mr+g+8][kk+tg+4];
                afL[mt][0] = AsL[mr+g  ][kk+tg  ];
                afL[mt][1] = AsL[mr+g+8][kk+tg  ];
                afL[mt][2] = AsL[mr+g  ][kk+tg+4];
                afL[mt][3] = AsL[mr+g+8][kk+tg+4];
            }
#pragma unroll
            for (int nt = 0; nt < 4; nt++){
                int nc = wn*32 + nt*8;
                unsigned bh0, bh1, bl0, bl1;
                if (TRANSB){
                    bh0 = BsH[nc+g][kk+tg]; bh1 = BsH[nc+g][kk+tg+4];
                    bl0 = BsL[nc+g][kk+tg]; bl1 = BsL[nc+g][kk+tg+4];
                } else {
                    bh0 = BsH[kk+tg][nc+g]; bh1 = BsH[kk+tg+4][nc+g];
                    bl0 = BsL[kk+tg][nc+g]; bl1 = BsL[kk+tg+4][nc+g];
                }
#pragma unroll
                for (int mt = 0; mt < 4; mt++){
                    mma_tf32(acc[mt][nt], afH[mt], bl0, bl1);
                    mma_tf32(acc[mt][nt], afL[mt], bh0, bh1);
                    mma_tf32(acc[mt][nt], afH[mt], bh0, bh1);
                }
            }
        }
        __syncthreads();
        if (kt + 1 < kiters){ storeA(); storeB(); __syncthreads(); }
    }

    // epilogue
#pragma unroll
    for (int mt = 0; mt < 4; mt++){
#pragma unroll
        for (int nt = 0; nt < 4; nt++){
            int r  = row0 + wm*64 + mt*16 + g;
            int c  = col0 + wn*32 + nt*8 + 2*tg;
            float b0 = bias ? bias[c]   : 0.f;
            float b1 = bias ? bias[c+1] : 0.f;
            if (r < M && c < N){
                float v0 = acc[mt][nt][0]*scale + b0;
                float v1 = acc[mt][nt][1]*scale + b1;
                if (act){ v0 = fmaxf(v0,0.f); v1 = fmaxf(v1,0.f); }
                Cb[(size_t)r*ldc + c]   = v0;
                Cb[(size_t)r*ldc + c+1] = v1;
            }
            int r2 = r + 8;
            if (r2 < M && c < N){
                float v2 = acc[mt][nt][2]*scale + b0;
                float v3 = acc[mt][nt][3]*scale + b1;
                if (act){ v2 = fmaxf(v2,0.f); v3 = fmaxf(v3,0.f); }
                Cb[(size_t)r2*ldc + c]   = v2;
                Cb[(size_t)r2*ldc + c+1] = v3;
            }
        }
    }
}

// ---------------- masked softmax ----------------
__global__ void softmax_kernel(float* __restrict__ Sc, int Tq, int Tk,
                               int causal, const int* __restrict__ evl)
{
    __shared__ float sh[32];
    int row = blockIdx.x;
    int t = row % Tq;
    int bh = row / Tq;
    int b = bh / HH;
    int vl = causal ? (t + 1) : evl[b];
    float* p = Sc + (size_t)row*Tk;
    int tid = threadIdx.x; // 128
    float v[8];
    float m = -3.4e38f;
#pragma unroll
    for (int i = 0; i < 8; i++){
        int c = tid + i*128;
        v[i] = p[c];
        if (c < vl) m = fmaxf(m, v[i]);
    }
    m = blockMax(m, sh);
    float s = 0.f;
#pragma unroll
    for (int i = 0; i < 8; i++){
        int c = tid + i*128;
        float e = (c < vl) ? expf(v[i] - m) : 0.f;
        v[i] = e; s += e;
    }
    s = blockSum(s, sh);
    float inv = 1.f / s;
#pragma unroll
    for (int i = 0; i < 8; i++) p[tid + i*128] = v[i] * inv;
}

// ---------------- LN ----------------
__global__ void ln_kernel(const float* __restrict__ A, const float* __restrict__ Bm, float sB,
                          const float* __restrict__ gw, const float* __restrict__ bw,
                          float* __restrict__ Out)
{
    __shared__ float sh[32];
    int row = blockIdx.x;
    int tid = threadIdx.x;   // 256
    float4 a4 = *(const float4*)(A + (size_t)row*DD + tid*4);
    float x[4] = {a4.x, a4.y, a4.z, a4.w};
    if (Bm){
        float4 b4 = *(const float4*)(Bm + (size_t)row*DD + tid*4);
        x[0] += sB*b4.x; x[1] += sB*b4.y; x[2] += sB*b4.z; x[3] += sB*b4.w;
    }
    float s = x[0]+x[1]+x[2]+x[3];
    s = blockSum(s, sh);
    float mean = s * (1.f/DD);
    float q = 0.f;
#pragma unroll
    for (int i = 0; i < 4; i++){ float d = x[i]-mean; q += d*d; }
    q = blockSum(q, sh);
    float rstd = rsqrtf(q * (1.f/DD) + 1e-5f);
#pragma unroll
    for (int i = 0; i < 4; i++){
        int c = tid*4 + i;
        Out[(size_t)row*DD + c] = (x[i]-mean)*rstd*gw[c] + bw[c];
    }
}

// ---------------- concat ----------------
__global__ void concat_kernel(const float* __restrict__ Y, const float* __restrict__ intent,
                              float* __restrict__ Yi)
{
    int i = blockIdx.x*blockDim.x + threadIdx.x;
    if (i >= BT*DCc) return;
    int row = i / DCc, c = i % DCc;
    float val;
    if (c < DD) val = Y[(size_t)row*DD + c];
    else { int b = row / TT; val = intent[b*DIi + (c - DD)]; }
    Yi[i] = val;
}

// ---------------- ssc ----------------
__global__ void ssc_kernel(const float* __restrict__ QS, const float* __restrict__ KS,
                           float* __restrict__ SSC)
{
    __shared__ float qsh[DD];
    int row = blockIdx.x;
    int b = row / TT;
    int tid = threadIdx.x;  // 256
    *(float4*)&qsh[tid*4] = *(const float4*)(QS + (size_t)row*DD + tid*4);
    __syncthreads();
    int w = tid >> 5, lane = tid & 31;
    for (int ss = w; ss < SSt; ss += 8){
        const float* kr = KS + ((size_t)b*SSt + ss)*DD;
        float sum = 0.f;
        for (int j = lane*4; j < DD; j += 128){
            float4 kv = *(const float4*)(kr + j);
            float4 qv = *(const float4*)&qsh[j];
            sum += qv.x*kv.x + qv.y*kv.y + qv.z*kv.z + qv.w*kv.w;
        }
        sum = warpRedSum(sum);
        if (lane == 0) SSC[row*SSt + ss] = sum * (1.f/32.f);
    }
}

// ---------------- topk select ----------------
__global__ void sel_topk_kernel(const float* __restrict__ SSC, const float* __restrict__ TSC,
                                const int* __restrict__ svl,
                                int* __restrict__ OutIdx, float* __restrict__ OutW,
                                int* __restrict__ OutCnt)
{
    __shared__ float s_v[SSt];
    __shared__ float s_sw[SSt];
    __shared__ int   s_rank[SSt];
    __shared__ float s_tv[SSt][16];
    __shared__ int   s_ti[SSt][16];
    int row = blockIdx.x;
    int b = row / TT;
    int tid = threadIdx.x;   // 512
    int w = tid >> 5, lane = tid & 31;
    if (tid < SSt){
        float val = SSC[row*SSt + tid];
        if (tid >= svl[b]) val = NEGV;
        s_v[tid] = val;
    }
    __syncthreads();
    if (tid < SSt){
        float myv = s_v[tid];
        int cnt = 0;
        float m = -3.4e38f;
#pragma unroll
        for (int j = 0; j < SSt; j++){
            float o = s_v[j];
            if (o > myv || (o == myv && j < tid)) cnt++;
            m = fmaxf(m, o);
        }
        s_sw[tid] = (cnt < 8) ? expf(myv - m) : 0.f;
    }
    __syncthreads();
    if (tid == 0){
        float den = 0.f;
        for (int j = 0; j < SSt; j++) den += s_sw[j];
        float inv = 1.f/den;
        int r = 0;
        for (int j = 0; j < SSt; j++){
            float swv = s_sw[j]*inv;
            s_sw[j] = swv;
            s_rank[j] = r;
            if (swv > 0.f) r++;
        }
        OutCnt[row] = r*16;
    }
    __syncthreads();
    float swv = s_sw[w];
    if (swv > 0.f){
        const float* tr = TSC + ((size_t)row*SSt + w)*NNtk;
        float vloc[8];
#pragma unroll
        for (int r2 = 0; r2 < 8; r2++) vloc[r2] = tr[r2*32 + lane];
        for (int it = 0; it < 16; it++){
            float bv = -3.4e38f; int bi = 1 << 30;
#pragma unroll
            for (int r2 = 0; r2 < 8; r2++){
                if (vloc[r2] > bv){ bv = vloc[r2]; bi = r2*32 + lane; }
            }
#pragma unroll
            for (int off = 16; off > 0; off >>= 1){
                float ov = __shfl_xor_sync(0xffffffffu, bv, off);
                int   oi = __shfl_xor_sync(0xffffffffu, bi, off);
                if (ov > bv || (ov == bv && oi < bi)){ bv = ov; bi = oi; }
            }
            if (lane == 0){ s_tv[w][it] = bv; s_ti[w][it] = bi; }
            if ((bi & 31) == lane) vloc[bi >> 5] = -3.4e38f;
        }
        __syncwarp();
        float m2 = s_tv[w][0];
        float e2 = (lane < 16) ? expf(s_tv[w][lane] - m2) : 0.f;
        float den2 = warpRedSum(e2);
        if (lane < 16){
            int base = s_rank[w]*16;
            OutW[row*128 + base + lane]   = swv * e2 / den2;
            OutIdx[row*128 + base + lane] = w*NNtk + s_ti[w][lane];
        }
    }
}

// ---------------- sparse gather y2s ----------------
__global__ void gather_y2s_kernel(const int* __restrict__ Idx, const float* __restrict__ Wt,
                                  const int* __restrict__ Cnt, const float* __restrict__ VV,
                                  float* __restrict__ Out)
{
    __shared__ int   sh_i[128];
    __shared__ float sh_w[128];
    int row = blockIdx.x;
    int b = row / TT;
    int tid = threadIdx.x; // 256
    int cnt = Cnt[row];
    if (tid < 128){ sh_i[tid] = Idx[row*128 + tid]; sh_w[tid] = Wt[row*128 + tid]; }
    __syncthreads();
    const float* vb = VV + (size_t)b*SSt*NNtk*DD;
    float4 acc = make_float4(0.f,0.f,0.f,0.f);
    int c4 = tid*4;
    for (int e = 0; e < cnt; e++){
        float wv = sh_w[e];
        float4 x4 = *(const float4*)(vb + (size_t)sh_i[e]*DD + c4);
        acc.x += wv*x4.x; acc.y += wv*x4.y; acc.z += wv*x4.z; acc.w += wv*x4.w;
    }
    *(float4*)(Out + (size_t)row*DD + c4) = acc;
}

// ---------------- gate ----------------
__global__ void gate_kernel(const float* __restrict__ Y2S, const float* __restrict__ Y2E,
                            const float* __restrict__ Wg, float* __restrict__ Y2)
{
    __shared__ float sh[32];
    int row = blockIdx.x;
    int tid = threadIdx.x; // 256
    int c4 = tid*4;
    float4 a  = *(const float4*)(Y2S + (size_t)row*DD + c4);
    float4 b4 = *(const float4*)(Y2E + (size_t)row*DD + c4);
    float4 w1 = *(const float4*)(Wg + c4);
    float4 w2 = *(const float4*)(Wg + DD + c4);
    float part = a.x*w1.x + a.y*w1.y + a.z*w1.z + a.w*w1.w
               + b4.x*w2.x + b4.y*w2.y + b4.z*w2.z + b4.w*w2.w;
    float dot = blockSum(part, sh);
    float gv = 1.f/(1.f + expf(-dot));
    float4 o;
    o.x = gv*a.x + (1.f-gv)*b4.x;
    o.y = gv*a.y + (1.f-gv)*b4.y;
    o.z = gv*a.z + (1.f-gv)*b4.z;
    o.w = gv*a.w + (1.f-gv)*b4.w;
    *(float4*)(Y2 + (size_t)row*DD + c4) = o;
}

// ---------------- launch ----------------
extern "C" void kernel_launch(void* const* d_in, const int* in_sizes, int n_in,
                              void* d_out, int out_size)
{
    const float* x        = (const float*)d_in[0];
    const float* stat_enc = (const float*)d_in[1];
    const float* ex       = (const float*)d_in[2];
    const float* stat_ft  = (const float*)d_in[3];
    const float* intent   = (const float*)d_in[4];
    const float* Wq1=(const float*)d_in[5],  *Wk1=(const float*)d_in[6];
    const float* Wv1=(const float*)d_in[7],  *Wo1=(const float*)d_in[8];
    const float* Wq_stat=(const float*)d_in[9],  *Wq_token=(const float*)d_in[10];
    const float* Wk_stat=(const float*)d_in[11], *Wk_token=(const float*)d_in[12];
    const float* Wv_sel=(const float*)d_in[13],  *Wo_sel=(const float*)d_in[14];
    const float* Wq2=(const float*)d_in[15], *Wk2=(const float*)d_in[16];
    const float* Wv2=(const float*)d_in[17], *Wo2=(const float*)d_in[18];
    const float* Wg=(const float*)d_in[19];
    const float* W1=(const float*)d_in[20], *b1=(const float*)d_in[21];
    const float* W2=(const float*)d_in[22], *b2=(const float*)d_in[23];
    const float* w_g1=(const float*)d_in[24], *w_be1=(const float*)d_in[25];
    const float* w_g2=(const float*)d_in[26], *w_be2=(const float*)d_in[27];
    const float* w_g3=(const float*)d_in[28], *w_be3=(const float*)d_in[29];
    const int* svl = (const int*)d_in[30];
    const int* evl = (const int*)d_in[31];
    float* out = (float*)d_out;

    float *pq,*pk,*pv,*psc,*pm,*px2,*py,*pyi,*pqs,*pqt,*pks,*pkt,*pvv,*ptsc,*pssc;
    float *py2sr,*py2s,*py2e,*py2,*pz,*pffh,*pffo,*pselw;
    int *pselidx,*pselcnt;
    cudaGetSymbolAddress((void**)&pq, g_q);
    cudaGetSymbolAddress((void**)&pk, g_k);
    cudaGetSymbolAddress((void**)&pv, g_v);
    cudaGetSymbolAddress((void**)&psc, g_scores);
    cudaGetSymbolAddress((void**)&pm, g_merged);
    cudaGetSymbolAddress((void**)&px2, g_x2);
    cudaGetSymbolAddress((void**)&py, g_y);
    cudaGetSymbolAddress((void**)&pyi, g_yi);
    cudaGetSymbolAddress((void**)&pqs, g_qs);
    cudaGetSymbolAddress((void**)&pqt, g_qt);
    cudaGetSymbolAddress((void**)&pks, g_ksf);
    cudaGetSymbolAddress((void**)&pkt, g_kt);
    cudaGetSymbolAddress((void**)&pvv, g_vv);
    cudaGetSymbolAddress((void**)&ptsc, g_tsc);
    cudaGetSymbolAddress((void**)&pssc, g_ssc);
    cudaGetSymbolAddress((void**)&pselw, g_selw);
    cudaGetSymbolAddress((void**)&pselidx, g_selidx);
    cudaGetSymbolAddress((void**)&pselcnt, g_selcnt);
    cudaGetSymbolAddress((void**)&py2sr, g_y2s_raw);
    cudaGetSymbolAddress((void**)&py2s, g_y2s);
    cudaGetSymbolAddress((void**)&py2e, g_y2e);
    cudaGetSymbolAddress((void**)&py2, g_y2);
    cudaGetSymbolAddress((void**)&pz, g_z);
    cudaGetSymbolAddress((void**)&pffh, g_ffh);
    cudaGetSymbolAddress((void**)&pffo, g_ffo);

    auto G = [&](const float* A, const float* Bm, float* C, int M, int Nn, int K,
                 const float* bias, int act){
        dim3 grid((Nn + 127)/128, (M + 127)/128, 1);
        gemm_tf32<128,128,false><<<grid, 256>>>(A, Bm, C, M, Nn, K, K, Nn, Nn, 1,
                                                0,0,0,0,0,0, bias, 1.f, act);
    };

    // ---- self attention ----
    G(x, Wq1, pq, BT, DD, DD, nullptr, 0);
    G(x, Wk1, pk, BT, DD, DD, nullptr, 0);
    G(x, Wv1, pv, BT, DD, DD, nullptr, 0);
    gemm_tf32<128,128,true><<<dim3(TT/128, TT/128, BB*HH), 256>>>(
        pq, pk, psc, TT, TT, DHh, DD, DD, TT, HH,
        (size_t)TT*DD, (size_t)DHh, (size_t)TT*DD, (size_t)DHh,
        (size_t)HH*TT*TT, (size_t)TT*TT, nullptr, 0.125f, 0);
    softmax_kernel<<<BB*HH*TT, 128>>>(psc, TT, TT, 1, nullptr);
    gemm_tf32<128,64,false><<<dim3(1, TT/128, BB*HH), 128>>>(
        psc, pv, pm, TT, DHh, TT, TT, DD, DD, HH,
        (size_t)HH*TT*TT, (size_t)TT*TT, (size_t)TT*DD, (size_t)DHh,
        (size_t)TT*DD, (size_t)DHh, nullptr, 1.f, 0);
    G(pm, Wo1, px2, BT, DD, DD, nullptr, 0);
    ln_kernel<<<BT, 256>>>(x, px2, 1.f, w_g1, w_be1, py);

    // ---- selective hierarchical top-k ----
    concat_kernel<<<(BT*DCc + 255)/256, 256>>>(py, intent, pyi);
    G(pyi, Wq_stat, pqs, BT, DD, DCc, nullptr, 0);
    G(pyi, Wq_token, pqt, BT, DD, DCc, nullptr, 0);
    G(stat_ft, Wk_stat, pks, BB*SSt, DD, DD, nullptr, 0);
    G(stat_enc, Wk_token, pkt, BSN, DD, DD, nullptr, 0);
    G(stat_enc, Wv_sel, pvv, BSN, DD, DD, nullptr, 0);
    ssc_kernel<<<BT, 256>>>(pqs, pks, pssc);
    gemm_tf32<128,128,true><<<dim3((SSt*NNtk)/128, TT/128, BB), 256>>>(
        pqt, pkt, ptsc, TT, SSt*NNtk, DD, DD, DD, SSt*NNtk, 1,
        (size_t)TT*DD, 0, (size_t)SSt*NNtk*DD, 0,
        (size_t)TT*SSt*NNtk, 0, nullptr, 1.f/32.f, 0);
    sel_topk_kernel<<<BT, 512>>>(pssc, ptsc, svl, pselidx, pselw, pselcnt);
    gather_y2s_kernel<<<BT, 256>>>(pselidx, pselw, pselcnt, pvv, py2sr);
    G(py2sr, Wo_sel, py2s, BT, DD, DD, nullptr, 0);

    // ---- exemplar cross attention ----
    G(pyi, Wq2, pq, BT, DD, DCc, nullptr, 0);
    G(ex, Wk2, pk, BB*EEx, DD, DD, nullptr, 0);
    G(ex, Wv2, pv, BB*EEx, DD, DD, nullptr, 0);
    gemm_tf32<128,128,true><<<dim3(EEx/128, TT/128, BB*HH), 256>>>(
        pq, pk, psc, TT, EEx, DHh, DD, DD, EEx, HH,
        (size_t)TT*DD, (size_t)DHh, (size_t)EEx*DD, (size_t)DHh,
        (size_t)HH*TT*EEx, (size_t)TT*EEx, nullptr, 0.125f, 0);
    softmax_kernel<<<BB*HH*TT, 128>>>(psc, TT, EEx, 0, evl);
    gemm_tf32<128,64,false><<<dim3(1, TT/128, BB*HH), 128>>>(
        psc, pv, pm, TT, DHh, EEx, EEx, DD, DD, HH,
        (size_t)HH*TT*EEx, (size_t)TT*EEx, (size_t)EEx*DD, (size_t)DHh,
        (size_t)TT*DD, (size_t)DHh, nullptr, 1.f, 0);
    G(pm, Wo2, py2e, BT, DD, DD, nullptr, 0);

    // ---- gate, LN, FFN, LN ----
    gate_kernel<<<BT, 256>>>(py2s, py2e, Wg, py2);
    ln_kernel<<<BT, 256>>>(py, py2, 2.f, w_g2, w_be2, pz);
    G(pz, W1, pffh, BT, DFFf, DD, b1, 1);
    G(pffh, W2, pffo, BT, DD, DFFf, b2, 0);
    ln_kernel<<<BT, 256>>>(pz, pffo, 1.f, w_g3, w_be3, out);
}

// round 4
// speedup vs baseline: 1.1722x; 1.0871x over previous
#include <cuda_runtime.h>
#include <cuda_bf16.h>
#include <math.h>

#define BB   4
#define TT   1024
#define DD   1024
#define DIi  256
#define DCc  1280
#define DFFf 4096
#define HH   16
#define DHh  64
#define SSt  16
#define NNtk 256
#define EEx  1024
#define BT   (BB*TT)            /* 4096  */
#define BSN  (BB*SSt*NNtk)      /* 16384 */
#define NEGV -1e6f
#define BKk  16

// ---------------- scratch ----------------
__device__ float g_q[BT*DD];
__device__ float g_k[BT*DD];
__device__ float g_v[BT*DD];
__device__ float g_scores[(size_t)BB*HH*TT*TT];
__device__ float g_merged[BT*DD];
__device__ float g_x2[BT*DD];
__device__ float g_y[BT*DD];
__device__ float g_yi[BT*DCc];
__device__ float g_qs[BT*DD];
__device__ float g_qt[BT*DD];
__device__ float g_ksf[BB*SSt*DD];
__device__ float g_kt[(size_t)BSN*DD];
__device__ float g_vv[(size_t)BSN*DD];
__device__ float g_tsc[(size_t)BT*SSt*NNtk];
__device__ float g_ssc[BT*SSt];
__device__ int   g_selidx[BT*128];
__device__ float g_selw[BT*128];
__device__ int   g_selcnt[BT];
__device__ float g_y2s_raw[BT*DD];
__device__ float g_y2s[BT*DD];
__device__ float g_y2e[BT*DD];
__device__ float g_y2[BT*DD];
__device__ float g_z[BT*DD];
__device__ float g_ffh[(size_t)BT*DFFf];
__device__ float g_ffo[BT*DD];

// ---------------- helpers ----------------
__device__ __forceinline__ void split_tf(float f, unsigned& hi, unsigned& lo){
    unsigned h; asm("cvt.rna.tf32.f32 %0, %1;" : "=r"(h) : "f"(f));
    float hf = __uint_as_float(h);
    float lf = f - hf;
    unsigned l; asm("cvt.rna.tf32.f32 %0, %1;" : "=r"(l) : "f"(lf));
    hi = h; lo = l;
}
__device__ __forceinline__ void mma_tf32(float c[4], const unsigned a[4], unsigned b0, unsigned b1){
    asm volatile("mma.sync.aligned.m16n8k8.row.col.f32.tf32.tf32.f32 "
        "{%0,%1,%2,%3},{%4,%5,%6,%7},{%8,%9},{%0,%1,%2,%3};\n"
        : "+f"(c[0]), "+f"(c[1]), "+f"(c[2]), "+f"(c[3])
        : "r"(a[0]), "r"(a[1]), "r"(a[2]), "r"(a[3]), "r"(b0), "r"(b1));
}
__device__ __forceinline__ void mma_bf16(float c[4], const unsigned a[4], unsigned b0, unsigned b1){
    asm volatile("mma.sync.aligned.m16n8k16.row.col.f32.bf16.bf16.f32 "
        "{%0,%1,%2,%3},{%4,%5,%6,%7},{%8,%9},{%0,%1,%2,%3};\n"
        : "+f"(c[0]), "+f"(c[1]), "+f"(c[2]), "+f"(c[3])
        : "r"(a[0]), "r"(a[1]), "r"(a[2]), "r"(a[3]), "r"(b0), "r"(b1));
}
__device__ __forceinline__ void split_bf2(float a, float b, unsigned& hi, unsigned& lo){
    __nv_bfloat16 ha = __float2bfloat16(a);
    __nv_bfloat16 hb = __float2bfloat16(b);
    __nv_bfloat16 la = __float2bfloat16(a - __bfloat162float(ha));
    __nv_bfloat16 lb = __float2bfloat16(b - __bfloat162float(hb));
    hi = (unsigned)__bfloat16_as_ushort(ha) | ((unsigned)__bfloat16_as_ushort(hb) << 16);
    lo = (unsigned)__bfloat16_as_ushort(la) | ((unsigned)__bfloat16_as_ushort(lb) << 16);
}
__device__ __forceinline__ void split_bf1(float a, unsigned short& hi, unsigned short& lo){
    __nv_bfloat16 h = __float2bfloat16(a);
    __nv_bfloat16 l = __float2bfloat16(a - __bfloat162float(h));
    hi = __bfloat16_as_ushort(h);
    lo = __bfloat16_as_ushort(l);
}
__device__ __forceinline__ float warpRedSum(float v){
#pragma unroll
    for (int o = 16; o > 0; o >>= 1) v += __shfl_xor_sync(0xffffffffu, v, o);
    return v;
}
__device__ __forceinline__ float warpRedMax(float v){
#pragma unroll
    for (int o = 16; o > 0; o >>= 1) v = fmaxf(v, __shfl_xor_sync(0xffffffffu, v, o));
    return v;
}
__device__ __forceinline__ float blockSum(float v, float* sh){
    int lane = threadIdx.x & 31, w = threadIdx.x >> 5;
    v = warpRedSum(v);
    if (lane == 0) sh[w] = v;
    __syncthreads();
    if (w == 0){
        int nw = blockDim.x >> 5;
        float r = (lane < nw) ? sh[lane] : 0.f;
        r = warpRedSum(r);
        if (lane == 0) sh[0] = r;
    }
    __syncthreads();
    float r = sh[0];
    __syncthreads();
    return r;
}
__device__ __forceinline__ float blockMax(float v, float* sh){
    int lane = threadIdx.x & 31, w = threadIdx.x >> 5;
    v = warpRedMax(v);
    if (lane == 0) sh[w] = v;
    __syncthreads();
    if (w == 0){
        int nw = blockDim.x >> 5;
        float r = (lane < nw) ? sh[lane] : -3.4e38f;
        r = warpRedMax(r);
        if (lane == 0) sh[0] = r;
    }
    __syncthreads();
    float r = sh[0];
    __syncthreads();
    return r;
}

// ================= 3xTF32 tensor-core GEMM (fp32-accurate) =================
template<int BM, int BN, bool TRANSB>
__global__ void __launch_bounds__((BM/64)*(BN/32)*32, 2)
gemm_tf32(const float* __restrict__ A, const float* __restrict__ B, float* __restrict__ C,
          int M, int N, int K, int lda, int ldb, int ldc, int NH,
          size_t sAb, size_t sAh, size_t sBb, size_t sBh, size_t sCb, size_t sCh,
          const float* __restrict__ bias, float scale, int act)
{
    constexpr int NWN = BN/32, NWM = BM/64, NW = NWN*NWM, NTH = NW*32;
    constexpr int AV  = (BM*BKk/4)/NTH;
    constexpr int BV  = (TRANSB ? BN*BKk/4 : (BKk*BN/4))/NTH;
    constexpr int BROWS = TRANSB ? BN : BKk;
    constexpr int BCOLS = TRANSB ? (BKk+4) : (BN+8);

    __shared__ unsigned AsH[BM][BKk+4];
    __shared__ unsigned AsL[BM][BKk+4];
    __shared__ unsigned BsH[BROWS][BCOLS];
    __shared__ unsigned BsL[BROWS][BCOLS];

    int z = blockIdx.z;
    const float* Ab = A + (size_t)(z/NH)*sAb + (size_t)(z%NH)*sAh;
    const float* Bb = B + (size_t)(z/NH)*sBb + (size_t)(z%NH)*sBh;
    float*       Cb = C + (size_t)(z/NH)*sCb + (size_t)(z%NH)*sCh;

    int tid = threadIdx.x, lane = tid & 31, wid = tid >> 5;
    int wn = wid % NWN, wm = wid / NWN;
    int row0 = blockIdx.y * BM, col0 = blockIdx.x * BN;
    int g = lane >> 2, tg = lane & 3;

    float acc[4][4][4] = {};
    float4 ra[AV], rb[BV];

    auto fetchA = [&](int kk){
#pragma unroll
        for (int v = 0; v < AV; v++){
            int i = tid + v*NTH;
            int r = i >> 2, c = (i & 3) * 4;
            int gr = row0 + r;
            ra[v] = (gr < M) ? *(const float4*)(Ab + (size_t)gr*lda + kk + c)
                             : make_float4(0.f,0.f,0.f,0.f);
        }
    };
    auto storeA = [&](){
#pragma unroll
        for (int v = 0; v < AV; v++){
            int i = tid + v*NTH;
            int r = i >> 2, c = (i & 3) * 4;
            split_tf(ra[v].x, AsH[r][c+0], AsL[r][c+0]);
            split_tf(ra[v].y, AsH[r][c+1], AsL[r][c+1]);
            split_tf(ra[v].z, AsH[r][c+2], AsL[r][c+2]);
            split_tf(ra[v].w, AsH[r][c+3], AsL[r][c+3]);
        }
    };
    auto fetchB = [&](int kk){
        if (TRANSB){
#pragma unroll
            for (int v = 0; v < BV; v++){
                int i = tid + v*NTH;
                int r = i >> 2, c = (i & 3) * 4;
                int gr = col0 + r;
                rb[v] = (gr < N) ? *(const float4*)(Bb + (size_t)gr*ldb + kk + c)
                                 : make_float4(0.f,0.f,0.f,0.f);
            }
        } else {
            constexpr int VPR = BN/4;
#pragma unroll
            for (int v = 0; v < BV; v++){
                int i = tid + v*NTH;
                int r = i / VPR, c = (i % VPR) * 4;
                int gc = col0 + c;
                rb[v] = (gc < N) ? *(const float4*)(Bb + (size_t)(kk+r)*ldb + gc)
                                 : make_float4(0.f,0.f,0.f,0.f);
            }
        }
    };
    auto storeB = [&](){
        if (TRANSB){
#pragma unroll
            for (int v = 0; v < BV; v++){
                int i = tid + v*NTH;
                int r = i >> 2, c = (i & 3) * 4;
                split_tf(rb[v].x, BsH[r][c+0], BsL[r][c+0]);
                split_tf(rb[v].y, BsH[r][c+1], BsL[r][c+1]);
                split_tf(rb[v].z, BsH[r][c+2], BsL[r][c+2]);
                split_tf(rb[v].w, BsH[r][c+3], BsL[r][c+3]);
            }
        } else {
            constexpr int VPR = BN/4;
#pragma unroll
            for (int v = 0; v < BV; v++){
                int i = tid + v*NTH;
                int r = i / VPR, c = (i % VPR) * 4;
                split_tf(rb[v].x, BsH[r][c+0], BsL[r][c+0]);
                split_tf(rb[v].y, BsH[r][c+1], BsL[r][c+1]);
                split_tf(rb[v].z, BsH[r][c+2], BsL[r][c+2]);
                split_tf(rb[v].w, BsH[r][c+3], BsL[r][c+3]);
            }
        }
    };

    fetchA(0); fetchB(0);
    storeA(); storeB();
    __syncthreads();

    int kiters = K / BKk;
    for (int kt = 0; kt < kiters; kt++){
        if (kt + 1 < kiters){ fetchA((kt+1)*BKk); fetchB((kt+1)*BKk); }
#pragma unroll
        for (int ks = 0; ks < BKk/8; ks++){
            int kk = ks * 8;
            unsigned afH[4][4], afL[4][4];
#pragma unroll
            for (int mt = 0; mt < 4; mt++){
                int mr = wm*64 + mt*16;
                afH[mt][0] = AsH[mr+g  ][kk+tg  ];
                afH[mt][1] = AsH[mr+g+8][kk+tg  ];
                afH[mt][2] = AsH[mr+g  ][kk+tg+4];
                afH[mt][3] = AsH[mr+g+8][kk+tg+4];
                afL[mt][0] = AsL[mr+g  ][kk+tg  ];
                afL[mt][1] = AsL[mr+g+8][kk+tg  ];
                afL[mt][2] = AsL[mr+g  ][kk+tg+4];
                afL[mt][3] = AsL[mr+g+8][kk+tg+4];
            }
#pragma unroll
            for (int nt = 0; nt < 4; nt++){
                int nc = wn*32 + nt*8;
                unsigned bh0, bh1, bl0, bl1;
                if (TRANSB){
                    bh0 = BsH[nc+g][kk+tg]; bh1 = BsH[nc+g][kk+tg+4];
                    bl0 = BsL[nc+g][kk+tg]; bl1 = BsL[nc+g][kk+tg+4];
                } else {
                    bh0 = BsH[kk+tg][nc+g]; bh1 = BsH[kk+tg+4][nc+g];
                    bl0 = BsL[kk+tg][nc+g]; bl1 = BsL[kk+tg+4][nc+g];
                }
#pragma unroll
                for (int mt = 0; mt < 4; mt++){
                    mma_tf32(acc[mt][nt], afH[mt], bl0, bl1);
                    mma_tf32(acc[mt][nt], afL[mt], bh0, bh1);
                    mma_tf32(acc[mt][nt], afH[mt], bh0, bh1);
                }
            }
        }
        __syncthreads();
        if (kt + 1 < kiters){ storeA(); storeB(); __syncthreads(); }
    }

#pragma unroll
    for (int mt = 0; mt < 4; mt++){
#pragma unroll
        for (int nt = 0; nt < 4; nt++){
            int r  = row0 + wm*64 + mt*16 + g;
            int c  = col0 + wn*32 + nt*8 + 2*tg;
            float b0 = bias ? bias[c]   : 0.f;
            float b1 = bias ? bias[c+1] : 0.f;
            if (r < M && c < N){
                float v0 = acc[mt][nt][0]*scale + b0;
                float v1 = acc[mt][nt][1]*scale + b1;
                if (act){ v0 = fmaxf(v0,0.f); v1 = fmaxf(v1,0.f); }
                Cb[(size_t)r*ldc + c]   = v0;
                Cb[(size_t)r*ldc + c+1] = v1;
            }
            int r2 = r + 8;
            if (r2 < M && c < N){
                float v2 = acc[mt][nt][2]*scale + b0;
                float v3 = acc[mt][nt][3]*scale + b1;
                if (act){ v2 = fmaxf(v2,0.f); v3 = fmaxf(v3,0.f); }
                Cb[(size_t)r2*ldc + c]   = v2;
                Cb[(size_t)r2*ldc + c+1] = v3;
            }
        }
    }
}

// ================= 3xBF16 tensor-core GEMM (~1e-5 accurate; for post-topk ops) ====
template<int BM, int BN, bool TRANSB>
__global__ void __launch_bounds__((BM/64)*(BN/32)*32, 2)
gemm_bf16(const float* __restrict__ A, const float* __restrict__ B, float* __restrict__ C,
          int M, int N, int K, int lda, int ldb, int ldc, int NH,
          size_t sAb, size_t sAh, size_t sBb, size_t sBh, size_t sCb, size_t sCh,
          const float* __restrict__ bias, float scale, int act)
{
    constexpr int NWN = BN/32, NWM = BM/64, NW = NWN*NWM, NTH = NW*32;
    constexpr int BKb = 16;
    constexpr int AV  = (BM*BKb/4)/NTH;
    constexpr int BV  = (TRANSB ? BN*BKb/4 : (BKb*BN/4))/NTH;

    // packed bf16x2 along K: 8 words of payload + 4 pad
    __shared__ unsigned AsH2[BM][12];
    __shared__ unsigned AsL2[BM][12];
    __shared__ unsigned BsH2[BN][12];
    __shared__ unsigned BsL2[BN][12];

    int z = blockIdx.z;
    const float* Ab = A + (size_t)(z/NH)*sAb + (size_t)(z%NH)*sAh;
    const float* Bb = B + (size_t)(z/NH)*sBb + (size_t)(z%NH)*sBh;
    float*       Cb = C + (size_t)(z/NH)*sCb + (size_t)(z%NH)*sCh;

    int tid = threadIdx.x, lane = tid & 31, wid = tid >> 5;
    int wn = wid % NWN, wm = wid / NWN;
    int row0 = blockIdx.y * BM, col0 = blockIdx.x * BN;
    int g = lane >> 4 ? 0 : 0; // placeholder, real below
    g = lane >> 2;
    int tg = lane & 3;

    float acc[4][4][4] = {};
    float4 ra[AV], rb[BV];

    auto fetchA = [&](int kk){
#pragma unroll
        for (int v = 0; v < AV; v++){
            int i = tid + v*NTH;
            int r = i >> 2, c = (i & 3) * 4;
            int gr = row0 + r;
            ra[v] = (gr < M) ? *(const float4*)(Ab + (size_t)gr*lda + kk + c)
                             : make_float4(0.f,0.f,0.f,0.f);
        }
    };
    auto storeA = [&](){
#pragma unroll
        for (int v = 0; v < AV; v++){
            int i = tid + v*NTH;
            int r = i >> 2, c2 = (i & 3) * 2;
            split_bf2(ra[v].x, ra[v].y, AsH2[r][c2],   AsL2[r][c2]);
            split_bf2(ra[v].z, ra[v].w, AsH2[r][c2+1], AsL2[r][c2+1]);
        }
    };
    auto fetchB = [&](int kk){
        if (TRANSB){
#pragma unroll
            for (int v = 0; v < BV; v++){
                int i = tid + v*NTH;
                int r = i >> 2, c = (i & 3) * 4;
                int gr = col0 + r;
                rb[v] = (gr < N) ? *(const float4*)(Bb + (size_t)gr*ldb + kk + c)
                                 : make_float4(0.f,0.f,0.f,0.f);
            }
        } else {
            constexpr int VPR = BN/4;
#pragma unroll
            for (int v = 0; v < BV; v++){
                int i = tid + v*NTH;
                int r = i / VPR, c = (i % VPR) * 4;
                int gc = col0 + c;
                rb[v] = (gc < N) ? *(const float4*)(Bb + (size_t)(kk+r)*ldb + gc)
                                 : make_float4(0.f,0.f,0.f,0.f);
            }
        }
    };
    auto storeB = [&](){
        if (TRANSB){
#pragma unroll
            for (int v = 0; v < BV; v++){
                int i = tid + v*NTH;
                int r = i >> 2, c2 = (i & 3) * 2;
                split_bf2(rb[v].x, rb[v].y, BsH2[r][c2],   BsL2[r][c2]);
                split_bf2(rb[v].z, rb[v].w, BsH2[r][c2+1], BsL2[r][c2+1]);
            }
        } else {
            constexpr int VPR = BN/4;
#pragma unroll
            for (int v = 0; v < BV; v++){
                int i = tid + v*NTH;
                int r = i / VPR, c = (i % VPR) * 4;
                float f[4] = {rb[v].x, rb[v].y, rb[v].z, rb[v].w};
#pragma unroll
                for (int j = 0; j < 4; j++){
                    unsigned short h, l;
                    split_bf1(f[j], h, l);
                    ((unsigned short*)&BsH2[c+j][r>>1])[r&1] = h;
                    ((unsigned short*)&BsL2[c+j][r>>1])[r&1] = l;
                }
            }
        }
    };

    fetchA(0); fetchB(0);
    storeA(); storeB();
    __syncthreads();

    int kiters = K / BKb;
    for (int kt = 0; kt < kiters; kt++){
        if (kt + 1 < kiters){ fetchA((kt+1)*BKb); fetchB((kt+1)*BKb); }
        {
            unsigned afH[4][4], afL[4][4];
#pragma unroll
            for (int mt = 0; mt < 4; mt++){
                int mr = wm*64 + mt*16;
                afH[mt][0] = AsH2[mr+g  ][tg  ];
                afH[mt][1] = AsH2[mr+g+8][tg  ];
                afH[mt][2] = AsH2[mr+g  ][tg+4];
                afH[mt][3] = AsH2[mr+g+8][tg+4];
                afL[mt][0] = AsL2[mr+g  ][tg  ];
                afL[mt][1] = AsL2[mr+g+8][tg  ];
                afL[mt][2] = AsL2[mr+g  ][tg+4];
                afL[mt][3] = AsL2[mr+g+8][tg+4];
            }
#pragma unroll
            for (int nt = 0; nt < 4; nt++){
                int nc = wn*32 + nt*8;
                unsigned bh0 = BsH2[nc+g][tg], bh1 = BsH2[nc+g][tg+4];
                unsigned bl0 = BsL2[nc+g][tg], bl1 = BsL2[nc+g][tg+4];
#pragma unroll
                for (int mt = 0; mt < 4; mt++){
                    mma_bf16(acc[mt][nt], afH[mt], bl0, bl1);
                    mma_bf16(acc[mt][nt], afL[mt], bh0, bh1);
                    mma_bf16(acc[mt][nt], afH[mt], bh0, bh1);
                }
            }
        }
        __syncthreads();
        if (kt + 1 < kiters){ storeA(); storeB(); __syncthreads(); }
    }

#pragma unroll
    for (int mt = 0; mt < 4; mt++){
#pragma unroll
        for (int nt = 0; nt < 4; nt++){
            int r  = row0 + wm*64 + mt*16 + g;
            int c  = col0 + wn*32 + nt*8 + 2*tg;
            float b0 = bias ? bias[c]   : 0.f;
            float b1 = bias ? bias[c+1] : 0.f;
            if (r < M && c < N){
                float v0 = acc[mt][nt][0]*scale + b0;
                float v1 = acc[mt][nt][1]*scale + b1;
                if (act){ v0 = fmaxf(v0,0.f); v1 = fmaxf(v1,0.f); }
                Cb[(size_t)r*ldc + c]   = v0;
                Cb[(size_t)r*ldc + c+1] = v1;
            }
            int r2 = r + 8;
            if (r2 < M && c < N){
                float v2 = acc[mt][nt][2]*scale + b0;
                float v3 = acc[mt][nt][3]*scale + b1;
                if (act){ v2 = fmaxf(v2,0.f); v3 = fmaxf(v3,0.f); }
                Cb[(size_t)r2*ldc + c]   = v2;
                Cb[(size_t)r2*ldc + c+1] = v3;
            }
        }
    }
}

// ---------------- masked softmax ----------------
__global__ void softmax_kernel(float* __restrict__ Sc, int Tq, int Tk,
                               int causal, const int* __restrict__ evl)
{
    __shared__ float sh[32];
    int row = blockIdx.x;
    int t = row % Tq;
    int bh = row / Tq;
    int b = bh / HH;
    int vl = causal ? (t + 1) : evl[b];
    float* p = Sc + (size_t)row*Tk;
    int tid = threadIdx.x; // 128
    float v[8];
    float m = -3.4e38f;
#pragma unroll
    for (int i = 0; i < 8; i++){
        int c = tid + i*128;
        v[i] = p[c];
        if (c < vl) m = fmaxf(m, v[i]);
    }
    m = blockMax(m, sh);
    float s = 0.f;
#pragma unroll
    for (int i = 0; i < 8; i++){
        int c = tid + i*128;
        float e = (c < vl) ? expf(v[i] - m) : 0.f;
        v[i] = e; s += e;
    }
    s = blockSum(s, sh);
    float inv = 1.f / s;
#pragma unroll
    for (int i = 0; i < 8; i++) p[tid + i*128] = v[i] * inv;
}

// ---------------- LN ----------------
__global__ void ln_kernel(const float* __restrict__ A, const float* __restrict__ Bm, float sB,
                          const float* __restrict__ gw, const float* __restrict__ bw,
                          float* __restrict__ Out)
{
    __shared__ float sh[32];
    int row = blockIdx.x;
    int tid = threadIdx.x;   // 256
    float4 a4 = *(const float4*)(A + (size_t)row*DD + tid*4);
    float x[4] = {a4.x, a4.y, a4.z, a4.w};
    if (Bm){
        float4 b4 = *(const float4*)(Bm + (size_t)row*DD + tid*4);
        x[0] += sB*b4.x; x[1] += sB*b4.y; x[2] += sB*b4.z; x[3] += sB*b4.w;
    }
    float s = x[0]+x[1]+x[2]+x[3];
    s = blockSum(s, sh);
    float mean = s * (1.f/DD);
    float q = 0.f;
#pragma unroll
    for (int i = 0; i < 4; i++){ float d = x[i]-mean; q += d*d; }
    q = blockSum(q, sh);
    float rstd = rsqrtf(q * (1.f/DD) + 1e-5f);
#pragma unroll
    for (int i = 0; i < 4; i++){
        int c = tid*4 + i;
        Out[(size_t)row*DD + c] = (x[i]-mean)*rstd*gw[c] + bw[c];
    }
}

// ---------------- concat ----------------
__global__ void concat_kernel(const float* __restrict__ Y, const float* __restrict__ intent,
                              float* __restrict__ Yi)
{
    int i = blockIdx.x*blockDim.x + threadIdx.x;
    if (i >= BT*DCc) return;
    int row = i / DCc, c = i % DCc;
    float val;
    if (c < DD) val = Y[(size_t)row*DD + c];
    else { int b = row / TT; val = intent[b*DIi + (c - DD)]; }
    Yi[i] = val;
}

// ---------------- ssc ----------------
__global__ void ssc_kernel(const float* __restrict__ QS, const float* __restrict__ KS,
                           float* __restrict__ SSC)
{
    __shared__ float qsh[DD];
    int row = blockIdx.x;
    int b = row / TT;
    int tid = threadIdx.x;  // 256
    *(float4*)&qsh[tid*4] = *(const float4*)(QS + (size_t)row*DD + tid*4);
    __syncthreads();
    int w = tid >> 5, lane = tid & 31;
    for (int ss = w; ss < SSt; ss += 8){
        const float* kr = KS + ((size_t)b*SSt + ss)*DD;
        float sum = 0.f;
        for (int j = lane*4; j < DD; j += 128){
            float4 kv = *(const float4*)(kr + j);
            float4 qv = *(const float4*)&qsh[j];
            sum += qv.x*kv.x + qv.y*kv.y + qv.z*kv.z + qv.w*kv.w;
        }
        sum = warpRedSum(sum);
        if (lane == 0) SSC[row*SSt + ss] = sum * (1.f/32.f);
    }
}

// ---------------- topk select ----------------
__global__ void sel_topk_kernel(const float* __restrict__ SSC, const float* __restrict__ TSC,
                                const int* __restrict__ svl,
                                int* __restrict__ OutIdx, float* __restrict__ OutW,
                                int* __restrict__ OutCnt)
{
    __shared__ float s_v[SSt];
    __shared__ float s_sw[SSt];
    __shared__ int   s_rank[SSt];
    __shared__ float s_tv[SSt][16];
    __shared__ int   s_ti[SSt][16];
    int row = blockIdx.x;
    int b = row / TT;
    int tid = threadIdx.x;   // 512
    int w = tid >> 5, lane = tid & 31;
    if (tid < SSt){
        float val = SSC[row*SSt + tid];
        if (tid >= svl[b]) val = NEGV;
        s_v[tid] = val;
    }
    __syncthreads();
    if (tid < SSt){
        float myv = s_v[tid];
        int cnt = 0;
        float m = -3.4e38f;
#pragma unroll
        for (int j = 0; j < SSt; j++){
            float o = s_v[j];
            if (o > myv || (o == myv && j < tid)) cnt++;
            m = fmaxf(m, o);
        }
        s_sw[tid] = (cnt < 8) ? expf(myv - m) : 0.f;
    }
    __syncthreads();
    if (tid == 0){
        float den = 0.f;
        for (int j = 0; j < SSt; j++) den += s_sw[j];
        float inv = 1.f/den;
        int r = 0;
        for (int j = 0; j < SSt; j++){
            float swv = s_sw[j]*inv;
            s_sw[j] = swv;
            s_rank[j] = r;
            if (swv > 0.f) r++;
        }
        OutCnt[row] = r*16;
    }
    __syncthreads();
    float swv = s_sw[w];
    if (swv > 0.f){
        const float* tr = TSC + ((size_t)row*SSt + w)*NNtk;
        float vloc[8];
#pragma unroll
        for (int r2 = 0; r2 < 8; r2++) vloc[r2] = tr[r2*32 + lane];
        for (int it = 0; it < 16; it++){
            float bv = -3.4e38f; int bi = 1 << 30;
#pragma unroll
            for (int r2 = 0; r2 < 8; r2++){
                if (vloc[r2] > bv){ bv = vloc[r2]; bi = r2*32 + lane; }
            }
#pragma unroll
            for (int off = 16; off > 0; off >>= 1){
                float ov = __shfl_xor_sync(0xffffffffu, bv, off);
                int   oi = __shfl_xor_sync(0xffffffffu, bi, off);
                if (ov > bv || (ov == bv && oi < bi)){ bv = ov; bi = oi; }
            }
            if (lane == 0){ s_tv[w][it] = bv; s_ti[w][it] = bi; }
            if ((bi & 31) == lane) vloc[bi >> 5] = -3.4e38f;
        }
        __syncwarp();
        float m2 = s_tv[w][0];
        float e2 = (lane < 16) ? expf(s_tv[w][lane] - m2) : 0.f;
        float den2 = warpRedSum(e2);
        if (lane < 16){
            int base = s_rank[w]*16;
            OutW[row*128 + base + lane]   = swv * e2 / den2;
            OutIdx[row*128 + base + lane] = w*NNtk + s_ti[w][lane];
        }
    }
}

// ---------------- sparse gather y2s ----------------
__global__ void gather_y2s_kernel(const int* __restrict__ Idx, const float* __restrict__ Wt,
                                  const int* __restrict__ Cnt, const float* __restrict__ VV,
                                  float* __restrict__ Out)
{
    __shared__ int   sh_i[128];
    __shared__ float sh_w[128];
    int row = blockIdx.x;
    int b = row / TT;
    int tid = threadIdx.x; // 256
    int cnt = Cnt[row];
    if (tid < 128){ sh_i[tid] = Idx[row*128 + tid]; sh_w[tid] = Wt[row*128 + tid]; }
    __syncthreads();
    const float* vb = VV + (size_t)b*SSt*NNtk*DD;
    float4 acc = make_float4(0.f,0.f,0.f,0.f);
    int c4 = tid*4;
    for (int e = 0; e < cnt; e++){
        float wv = sh_w[e];
        float4 x4 = *(const float4*)(vb + (size_t)sh_i[e]*DD + c4);
        acc.x += wv*x4.x; acc.y += wv*x4.y; acc.z += wv*x4.z; acc.w += wv*x4.w;
    }
    *(float4*)(Out + (size_t)row*DD + c4) = acc;
}

// ---------------- gate ----------------
__global__ void gate_kernel(const float* __restrict__ Y2S, const float* __restrict__ Y2E,
                            const float* __restrict__ Wg, float* __restrict__ Y2)
{
    __shared__ float sh[32];
    int row = blockIdx.x;
    int tid = threadIdx.x; // 256
    int c4 = tid*4;
    float4 a  = *(const float4*)(Y2S + (size_t)row*DD + c4);
    float4 b4 = *(const float4*)(Y2E + (size_t)row*DD + c4);
    float4 w1 = *(const float4*)(Wg + c4);
    float4 w2 = *(const float4*)(Wg + DD + c4);
    float part = a.x*w1.x + a.y*w1.y + a.z*w1.z + a.w*w1.w
               + b4.x*w2.x + b4.y*w2.y + b4.z*w2.z + b4.w*w2.w;
    float dot = blockSum(part, sh);
    float gv = 1.f/(1.f + expf(-dot));
    float4 o;
    o.x = gv*a.x + (1.f-gv)*b4.x;
    o.y = gv*a.y + (1.f-gv)*b4.y;
    o.z = gv*a.z + (1.f-gv)*b4.z;
    o.w = gv*a.w + (1.f-gv)*b4.w;
    *(float4*)(Y2 + (size_t)row*DD + c4) = o;
}

// ---------------- launch ----------------
extern "C" void kernel_launch(void* const* d_in, const int* in_sizes, int n_in,
                              void* d_out, int out_size)
{
    const float* x        = (const float*)d_in[0];
    const float* stat_enc = (const float*)d_in[1];
    const float* ex       = (const float*)d_in[2];
    const float* stat_ft  = (const float*)d_in[3];
    const float* intent   = (const float*)d_in[4];
    const float* Wq1=(const float*)d_in[5],  *Wk1=(const float*)d_in[6];
    const float* Wv1=(const float*)d_in[7],  *Wo1=(const float*)d_in[8];
    const float* Wq_stat=(const float*)d_in[9],  *Wq_token=(const float*)d_in[10];
    const float* Wk_stat=(const float*)d_in[11], *Wk_token=(const float*)d_in[12];
    const float* Wv_sel=(const float*)d_in[13],  *Wo_sel=(const float*)d_in[14];
    const float* Wq2=(const float*)d_in[15], *Wk2=(const float*)d_in[16];
    const float* Wv2=(const float*)d_in[17], *Wo2=(const float*)d_in[18];
    const float* Wg=(const float*)d_in[19];
    const float* W1=(const float*)d_in[20], *b1=(const float*)d_in[21];
    const float* W2=(const float*)d_in[22], *b2=(const float*)d_in[23];
    const float* w_g1=(const float*)d_in[24], *w_be1=(const float*)d_in[25];
    const float* w_g2=(const float*)d_in[26], *w_be2=(const float*)d_in[27];
    const float* w_g3=(const float*)d_in[28], *w_be3=(const float*)d_in[29];
    const int* svl = (const int*)d_in[30];
    const int* evl = (const int*)d_in[31];
    float* out = (float*)d_out;

    float *pq,*pk,*pv,*psc,*pm,*px2,*py,*pyi,*pqs,*pqt,*pks,*pkt,*pvv,*ptsc,*pssc;
    float *py2sr,*py2s,*py2e,*py2,*pz,*pffh,*pffo,*pselw;
    int *pselidx,*pselcnt;
    cudaGetSymbolAddress((void**)&pq, g_q);
    cudaGetSymbolAddress((void**)&pk, g_k);
    cudaGetSymbolAddress((void**)&pv, g_v);
    cudaGetSymbolAddress((void**)&psc, g_scores);
    cudaGetSymbolAddress((void**)&pm, g_merged);
    cudaGetSymbolAddress((void**)&px2, g_x2);
    cudaGetSymbolAddress((void**)&py, g_y);
    cudaGetSymbolAddress((void**)&pyi, g_yi);
    cudaGetSymbolAddress((void**)&pqs, g_qs);
    cudaGetSymbolAddress((void**)&pqt, g_qt);
    cudaGetSymbolAddress((void**)&pks, g_ksf);
    cudaGetSymbolAddress((void**)&pkt, g_kt);
    cudaGetSymbolAddress((void**)&pvv, g_vv);
    cudaGetSymbolAddress((void**)&ptsc, g_tsc);
    cudaGetSymbolAddress((void**)&pssc, g_ssc);
    cudaGetSymbolAddress((void**)&pselw, g_selw);
    cudaGetSymbolAddress((void**)&pselidx, g_selidx);
    cudaGetSymbolAddress((void**)&pselcnt, g_selcnt);
    cudaGetSymbolAddress((void**)&py2sr, g_y2s_raw);
    cudaGetSymbolAddress((void**)&py2s, g_y2s);
    cudaGetSymbolAddress((void**)&py2e, g_y2e);
    cudaGetSymbolAddress((void**)&py2, g_y2);
    cudaGetSymbolAddress((void**)&pz, g_z);
    cudaGetSymbolAddress((void**)&pffh, g_ffh);
    cudaGetSymbolAddress((void**)&pffo, g_ffo);

    // high-precision (3xTF32) plain GEMM — for everything upstream of top-k
    auto G = [&](const float* A, const float* Bm, float* C, int M, int Nn, int K,
                 const float* bias, int act){
        dim3 grid((Nn + 127)/128, (M + 127)/128, 1);
        gemm_tf32<128,128,false><<<grid, 256>>>(A, Bm, C, M, Nn, K, K, Nn, Nn, 1,
                                                0,0,0,0,0,0, bias, 1.f, act);
    };
    // fast (3xBF16) plain GEMM — for everything downstream of top-k
    auto GB = [&](const float* A, const float* Bm, float* C, int M, int Nn, int K,
                  const float* bias, int act){
        dim3 grid((Nn + 127)/128, (M + 127)/128, 1);
        gemm_bf16<128,128,false><<<grid, 256>>>(A, Bm, C, M, Nn, K, K, Nn, Nn, 1,
                                                0,0,0,0,0,0, bias, 1.f, act);
    };

    // ---- self attention (upstream of top-k: tf32) ----
    G(x, Wq1, pq, BT, DD, DD, nullptr, 0);
    G(x, Wk1, pk, BT, DD, DD, nullptr, 0);
    G(x, Wv1, pv, BT, DD, DD, nullptr, 0);
    gemm_tf32<128,128,true><<<dim3(TT/128, TT/128, BB*HH), 256>>>(
        pq, pk, psc, TT, TT, DHh, DD, DD, TT, HH,
        (size_t)TT*DD, (size_t)DHh, (size_t)TT*DD, (size_t)DHh,
        (size_t)HH*TT*TT, (size_t)TT*TT, nullptr, 0.125f, 0);
    softmax_kernel<<<BB*HH*TT, 128>>>(psc, TT, TT, 1, nullptr);
    gemm_tf32<128,64,false><<<dim3(1, TT/128, BB*HH), 128>>>(
        psc, pv, pm, TT, DHh, TT, TT, DD, DD, HH,
        (size_t)HH*TT*TT, (size_t)TT*TT, (size_t)TT*DD, (size_t)DHh,
        (size_t)TT*DD, (size_t)DHh, nullptr, 1.f, 0);
    G(pm, Wo1, px2, BT, DD, DD, nullptr, 0);
    ln_kernel<<<BT, 256>>>(x, px2, 1.f, w_g1, w_be1, py);

    // ---- selective hierarchical top-k ----
    concat_kernel<<<(BT*DCc + 255)/256, 256>>>(py, intent, pyi);
    G(pyi, Wq_stat, pqs, BT, DD, DCc, nullptr, 0);
    G(pyi, Wq_token, pqt, BT, DD, DCc, nullptr, 0);
    G(stat_ft, Wk_stat, pks, BB*SSt, DD, DD, nullptr, 0);
    G(stat_enc, Wk_token, pkt, BSN, DD, DD, nullptr, 0);
    GB(stat_enc, Wv_sel, pvv, BSN, DD, DD, nullptr, 0);   // values: post-topk use
    ssc_kernel<<<BT, 256>>>(pqs, pks, pssc);
    gemm_tf32<128,128,true><<<dim3((SSt*NNtk)/128, TT/128, BB), 256>>>(
        pqt, pkt, ptsc, TT, SSt*NNtk, DD, DD, DD, SSt*NNtk, 1,
        (size_t)TT*DD, 0, (size_t)SSt*NNtk*DD, 0,
        (size_t)TT*SSt*NNtk, 0, nullptr, 1.f/32.f, 0);
    sel_topk_kernel<<<BT, 512>>>(pssc, ptsc, svl, pselidx, pselw, pselcnt);
    gather_y2s_kernel<<<BT, 256>>>(pselidx, pselw, pselcnt, pvv, py2sr);
    GB(py2sr, Wo_sel, py2s, BT, DD, DD, nullptr, 0);

    // ---- exemplar cross attention (fully downstream: bf16) ----
    GB(pyi, Wq2, pq, BT, DD, DCc, nullptr, 0);
    GB(ex, Wk2, pk, BB*EEx, DD, DD, nullptr, 0);
    GB(ex, Wv2, pv, BB*EEx, DD, DD, nullptr, 0);
    gemm_bf16<128,128,true><<<dim3(EEx/128, TT/128, BB*HH), 256>>>(
        pq, pk, psc, TT, EEx, DHh, DD, DD, EEx, HH,
        (size_t)TT*DD, (size_t)DHh, (size_t)EEx*DD, (size_t)DHh,
        (size_t)HH*TT*EEx, (size_t)TT*EEx, nullptr, 0.125f, 0);
    softmax_kernel<<<BB*HH*TT, 128>>>(psc, TT, EEx, 0, evl);
    gemm_bf16<128,64,false><<<dim3(1, TT/128, BB*HH), 128>>>(
        psc, pv, pm, TT, DHh, EEx, EEx, DD, DD, HH,
        (size_t)HH*TT*EEx, (size_t)TT*EEx, (size_t)EEx*DD, (size_t)DHh,
        (size_t)TT*DD, (size_t)DHh, nullptr, 1.f, 0);
    GB(pm, Wo2, py2e, BT, DD, DD, nullptr, 0);

    // ---- gate, LN, FFN (downstream: bf16), LN ----
    gate_kernel<<<BT, 256>>>(py2s, py2e, Wg, py2);
    ln_kernel<<<BT, 256>>>(py, py2, 2.f, w_g2, w_be2, pz);
    GB(pz, W1, pffh, BT, DFFf, DD, b1, 1);
    GB(pffh, W2, pffo, BT, DD, DFFf, b2, 0);
    ln_kernel<<<BT, 256>>>(pz, pffo, 1.f, w_g3, w_be3, out);
}